// round 1
// baseline (speedup 1.0000x reference)
#include <cuda_runtime.h>
#include <cuda_bf16.h>

#define N_NODES 50000
#define N_EDGES 800000
#define IN_DIM 512
#define HEADS 4
#define OUT_DIM 64
#define HD 256  // HEADS*OUT_DIM

// ---------------- scratch (device globals; no runtime alloc) ----------------
__device__ float g_h[N_NODES * HD];          // 51.2 MB  projected features
__device__ float g_ssrc[N_NODES * HEADS];    // per-node src scores
__device__ float g_sdst[N_NODES * HEADS];    // per-node dst scores
__device__ float g_e[N_EDGES * HEADS];       // per-edge scores -> exp values
__device__ float g_max[N_NODES * HEADS];     // segment max over src
__device__ float g_sum[N_NODES * HEADS];     // segment sum over src

// ---------------- GEMM: h = x @ W  (M=50000, K=512, N=256) ----------------
#define BM 64
#define BN 64
#define BK 16

__global__ void gat_gemm_kernel(const float* __restrict__ X,
                                const float* __restrict__ W) {
    __shared__ float As[BK][BM + 4];  // [k][m], padded for bank behavior + alignment
    __shared__ float Bs[BK][BN];      // [k][n]

    const int tid = threadIdx.x;           // 256 threads
    const int bm = blockIdx.x * BM;
    const int bn = blockIdx.y * BN;

    // A-tile load mapping: each thread loads one float4 (4 consecutive k)
    const int a_m = tid >> 2;              // 0..63
    const int a_k = (tid & 3) * 4;         // 0,4,8,12
    // B-tile load mapping: one float4 along n
    const int b_k = tid >> 4;              // 0..15
    const int b_n = (tid & 15) * 4;        // 0..60

    // compute mapping: 4x4 microtile
    const int row0 = (tid >> 4) * 4;       // 0..60
    const int col0 = (tid & 15) * 4;       // 0..60

    float acc[4][4];
#pragma unroll
    for (int i = 0; i < 4; i++)
#pragma unroll
        for (int j = 0; j < 4; j++) acc[i][j] = 0.f;

    const int gm = bm + a_m;
    const bool a_valid = (gm < N_NODES);

    for (int kt = 0; kt < IN_DIM; kt += BK) {
        float4 av = make_float4(0.f, 0.f, 0.f, 0.f);
        if (a_valid)
            av = *(const float4*)(X + gm * IN_DIM + kt + a_k);
        As[a_k + 0][a_m] = av.x;
        As[a_k + 1][a_m] = av.y;
        As[a_k + 2][a_m] = av.z;
        As[a_k + 3][a_m] = av.w;

        float4 bv = *(const float4*)(W + (kt + b_k) * HD + bn + b_n);
        *(float4*)&Bs[b_k][b_n] = bv;

        __syncthreads();

#pragma unroll
        for (int k = 0; k < BK; k++) {
            float a0 = As[k][row0 + 0];
            float a1 = As[k][row0 + 1];
            float a2 = As[k][row0 + 2];
            float a3 = As[k][row0 + 3];
            float4 b = *(float4*)&Bs[k][col0];
            acc[0][0] += a0 * b.x; acc[0][1] += a0 * b.y; acc[0][2] += a0 * b.z; acc[0][3] += a0 * b.w;
            acc[1][0] += a1 * b.x; acc[1][1] += a1 * b.y; acc[1][2] += a1 * b.z; acc[1][3] += a1 * b.w;
            acc[2][0] += a2 * b.x; acc[2][1] += a2 * b.y; acc[2][2] += a2 * b.z; acc[2][3] += a2 * b.w;
            acc[3][0] += a3 * b.x; acc[3][1] += a3 * b.y; acc[3][2] += a3 * b.z; acc[3][3] += a3 * b.w;
        }
        __syncthreads();
    }

#pragma unroll
    for (int i = 0; i < 4; i++) {
        int m = bm + row0 + i;
        if (m < N_NODES) {
            float4 v = make_float4(acc[i][0], acc[i][1], acc[i][2], acc[i][3]);
            *(float4*)&g_h[m * HD + bn + col0] = v;
        }
    }
}

// ---------------- per-(node,head) attention scores ----------------
__global__ void gat_score_kernel(const float* __restrict__ a) {
    int i = blockIdx.x * blockDim.x + threadIdx.x;
    if (i >= N_NODES * HEADS) return;
    int node = i >> 2;
    int head = i & 3;
    const float* hp = g_h + node * HD + head * OUT_DIM;
    const float* asrc = a + head * (2 * OUT_DIM);
    const float* adst = asrc + OUT_DIM;
    float ss = 0.f, sd = 0.f;
#pragma unroll 8
    for (int d = 0; d < OUT_DIM; d++) {
        float hv = hp[d];
        ss += hv * asrc[d];
        sd += hv * adst[d];
    }
    g_ssrc[i] = ss;
    g_sdst[i] = sd;
}

// ---------------- init max/-inf, sum/0 ----------------
__global__ void gat_init_kernel() {
    int i = blockIdx.x * blockDim.x + threadIdx.x;
    if (i >= N_NODES * HEADS) return;
    g_max[i] = -__int_as_float(0x7f800000);  // -inf
    g_sum[i] = 0.f;
}

// ---------------- out = bias (broadcast) ----------------
__global__ void gat_outinit_kernel(float* __restrict__ out,
                                   const float* __restrict__ bias) {
    for (int i = blockIdx.x * blockDim.x + threadIdx.x; i < N_NODES * HD;
         i += gridDim.x * blockDim.x) {
        out[i] = bias[i & (HD - 1)];
    }
}

// ---------------- float atomic max via int/uint trick ----------------
__device__ __forceinline__ void atomicMaxF(float* addr, float v) {
    if (v >= 0.f)
        atomicMax((int*)addr, __float_as_int(v));
    else
        atomicMin((unsigned int*)addr, __float_as_uint(v));
}

// ---------------- edge pass 1: e = leaky_relu(s_src+s_dst), segment max ----
__global__ void gat_edgemax_kernel(const int* __restrict__ edges) {
    int e = blockIdx.x * blockDim.x + threadIdx.x;
    if (e >= N_EDGES) return;
    int src = edges[2 * e];
    int dst = edges[2 * e + 1];
#pragma unroll
    for (int h = 0; h < HEADS; h++) {
        float v = g_ssrc[src * HEADS + h] + g_sdst[dst * HEADS + h];
        v = (v > 0.f) ? v : 0.2f * v;
        g_e[e * HEADS + h] = v;
        atomicMaxF(&g_max[src * HEADS + h], v);
    }
}

// ---------------- edge pass 2: exp & segment sum ----------------
__global__ void gat_edgeexp_kernel(const int* __restrict__ edges) {
    int e = blockIdx.x * blockDim.x + threadIdx.x;
    if (e >= N_EDGES) return;
    int src = edges[2 * e];
#pragma unroll
    for (int h = 0; h < HEADS; h++) {
        float ex = __expf(g_e[e * HEADS + h] - g_max[src * HEADS + h]);
        g_e[e * HEADS + h] = ex;
        atomicAdd(&g_sum[src * HEADS + h], ex);
    }
}

// ---------------- edge pass 3: scatter messages (warp per edge) ----------
__global__ void gat_scatter_kernel(const int* __restrict__ edges,
                                   float* __restrict__ out) {
    int gt = blockIdx.x * blockDim.x + threadIdx.x;
    int e = gt >> 5;
    if (e >= N_EDGES) return;
    int lane = gt & 31;

    int src = edges[2 * e];
    int dst = edges[2 * e + 1];

    // lane covers cols [lane*8, lane*8+8); head = lane/8
    int head = lane >> 3;
    float alpha = g_e[e * HEADS + head] /
                  (g_sum[src * HEADS + head] + 1e-10f);

    const float* hp = g_h + src * HD + lane * 8;
    float* op = out + dst * HD + lane * 8;

    float4 v0 = *(const float4*)(hp);
    float4 v1 = *(const float4*)(hp + 4);
    atomicAdd(op + 0, alpha * v0.x);
    atomicAdd(op + 1, alpha * v0.y);
    atomicAdd(op + 2, alpha * v0.z);
    atomicAdd(op + 3, alpha * v0.w);
    atomicAdd(op + 4, alpha * v1.x);
    atomicAdd(op + 5, alpha * v1.y);
    atomicAdd(op + 6, alpha * v1.z);
    atomicAdd(op + 7, alpha * v1.w);
}

// ---------------- launch ----------------
extern "C" void kernel_launch(void* const* d_in, const int* in_sizes, int n_in,
                              void* d_out, int out_size) {
    const float* x     = (const float*)d_in[0];
    const int*   edges = (const int*)d_in[1];
    const float* W     = (const float*)d_in[2];
    const float* a     = (const float*)d_in[3];
    const float* bias  = (const float*)d_in[4];
    float* out = (float*)d_out;

    dim3 gemm_grid((N_NODES + BM - 1) / BM, HD / BN);
    gat_gemm_kernel<<<gemm_grid, 256>>>(x, W);

    int nh = N_NODES * HEADS;
    gat_score_kernel<<<(nh + 255) / 256, 256>>>(a);
    gat_init_kernel<<<(nh + 255) / 256, 256>>>();
    gat_outinit_kernel<<<4096, 256>>>(out, bias);

    gat_edgemax_kernel<<<(N_EDGES + 255) / 256, 256>>>(edges);
    gat_edgeexp_kernel<<<(N_EDGES + 255) / 256, 256>>>(edges);

    gat_scatter_kernel<<<(N_EDGES * 32 + 255) / 256, 256>>>(edges, out);
}

// round 2
// speedup vs baseline: 2.8006x; 2.8006x over previous
#include <cuda_runtime.h>
#include <cuda_bf16.h>
#include <cstdint>

#define N_NODES 50000
#define N_EDGES 800000
#define IN_DIM 512
#define HEADS 4
#define OUT_DIM 64
#define HD 256  // HEADS*OUT_DIM

// ---------------- scratch (device globals; no runtime alloc) ----------------
__device__ float g_h[N_NODES * HD];          // 51.2 MB  projected features
__device__ float g_ssrc[N_NODES * HEADS];
__device__ float g_sdst[N_NODES * HEADS];
__device__ float g_e[N_EDGES * HEADS];       // edge scores -> exp values
__device__ float g_max[N_NODES * HEADS];
__device__ float g_sum[N_NODES * HEADS];     // sum -> reciprocal

// ================= TF32 MMA GEMM: h = x @ W  (50000x512 @ 512x256) =========
// CTA tile 128x64, BK=32, 8 warps (4x2), warp tile 32x32, mma m16n8k8.
#define GBM 128
#define GBN 64
#define GBK 32

__device__ __forceinline__ uint32_t f32_to_tf32(float f) {
    uint32_t r;
    asm("cvt.rna.tf32.f32 %0, %1;" : "=r"(r) : "f"(f));
    return r;
}

__global__ __launch_bounds__(256) void gat_gemm_tf32_kernel(
    const float* __restrict__ X, const float* __restrict__ W) {
    __shared__ uint32_t As[GBM][GBK + 4];   // [m][k]
    __shared__ uint32_t Bs[GBK][GBN + 4];   // [k][n]

    const int tid = threadIdx.x;
    const int lane = tid & 31;
    const int warp = tid >> 5;
    const int warp_m = warp >> 1;          // 0..3
    const int warp_n = warp & 1;           // 0..1

    const int bm = blockIdx.x * GBM;
    const int bn = blockIdx.y * GBN;

    // accumulators: 2 m-tiles x 4 n-tiles x 4 regs
    float acc[2][4][4];
#pragma unroll
    for (int i = 0; i < 2; i++)
#pragma unroll
        for (int j = 0; j < 4; j++)
#pragma unroll
            for (int r = 0; r < 4; r++) acc[i][j][r] = 0.f;

    const int a_row_in = tid >> 3;         // 0..31 (stride 32 over 4 iters)
    const int a_k4 = (tid & 7) * 4;
    const int b_k_in = tid >> 4;           // 0..15 (stride 16 over 2 iters)
    const int b_n4 = (tid & 15) * 4;

    const int lg = lane >> 2;              // groupID 0..7
    const int lt = lane & 3;               // 0..3

    for (int kt = 0; kt < IN_DIM; kt += GBK) {
        // load A tile (128 x 32) with tf32 convert
#pragma unroll
        for (int i = 0; i < 4; i++) {
            int row = a_row_in + i * 32;
            int gm = bm + row;
            float4 v = make_float4(0.f, 0.f, 0.f, 0.f);
            if (gm < N_NODES)
                v = *(const float4*)(X + (size_t)gm * IN_DIM + kt + a_k4);
            As[row][a_k4 + 0] = f32_to_tf32(v.x);
            As[row][a_k4 + 1] = f32_to_tf32(v.y);
            As[row][a_k4 + 2] = f32_to_tf32(v.z);
            As[row][a_k4 + 3] = f32_to_tf32(v.w);
        }
        // load B tile (32 x 64)
#pragma unroll
        for (int i = 0; i < 2; i++) {
            int k = b_k_in + i * 16;
            float4 v = *(const float4*)(W + (size_t)(kt + k) * HD + bn + b_n4);
            Bs[k][b_n4 + 0] = f32_to_tf32(v.x);
            Bs[k][b_n4 + 1] = f32_to_tf32(v.y);
            Bs[k][b_n4 + 2] = f32_to_tf32(v.z);
            Bs[k][b_n4 + 3] = f32_to_tf32(v.w);
        }
        __syncthreads();

#pragma unroll
        for (int kk = 0; kk < GBK; kk += 8) {
            // A fragments for 2 m-tiles
            uint32_t af[2][4];
#pragma unroll
            for (int mt = 0; mt < 2; mt++) {
                int rb = warp_m * 32 + mt * 16;
                af[mt][0] = As[rb + lg][kk + lt];
                af[mt][1] = As[rb + lg + 8][kk + lt];
                af[mt][2] = As[rb + lg][kk + lt + 4];
                af[mt][3] = As[rb + lg + 8][kk + lt + 4];
            }
            // B fragments for 4 n-tiles
            uint32_t bf[4][2];
#pragma unroll
            for (int nt = 0; nt < 4; nt++) {
                int cb = warp_n * 32 + nt * 8;
                bf[nt][0] = Bs[kk + lt][cb + lg];
                bf[nt][1] = Bs[kk + lt + 4][cb + lg];
            }
#pragma unroll
            for (int mt = 0; mt < 2; mt++)
#pragma unroll
                for (int nt = 0; nt < 4; nt++) {
                    asm volatile(
                        "mma.sync.aligned.m16n8k8.row.col.f32.tf32.tf32.f32 "
                        "{%0,%1,%2,%3}, {%4,%5,%6,%7}, {%8,%9}, {%0,%1,%2,%3};"
                        : "+f"(acc[mt][nt][0]), "+f"(acc[mt][nt][1]),
                          "+f"(acc[mt][nt][2]), "+f"(acc[mt][nt][3])
                        : "r"(af[mt][0]), "r"(af[mt][1]), "r"(af[mt][2]),
                          "r"(af[mt][3]), "r"(bf[nt][0]), "r"(bf[nt][1]));
                }
        }
        __syncthreads();
    }

    // epilogue
#pragma unroll
    for (int mt = 0; mt < 2; mt++) {
#pragma unroll
        for (int nt = 0; nt < 4; nt++) {
            int row0 = bm + warp_m * 32 + mt * 16 + lg;
            int col = bn + warp_n * 32 + nt * 8 + 2 * lt;
            if (row0 < N_NODES) {
                float2 v = make_float2(acc[mt][nt][0], acc[mt][nt][1]);
                *(float2*)&g_h[(size_t)row0 * HD + col] = v;
            }
            int row1 = row0 + 8;
            if (row1 < N_NODES) {
                float2 v = make_float2(acc[mt][nt][2], acc[mt][nt][3]);
                *(float2*)&g_h[(size_t)row1 * HD + col] = v;
            }
        }
    }
}

// ---------------- per-(node,head) attention scores ----------------
__global__ void gat_score_kernel(const float* __restrict__ a) {
    int i = blockIdx.x * blockDim.x + threadIdx.x;
    if (i >= N_NODES * HEADS) return;
    int node = i >> 2;
    int head = i & 3;
    const float* hp = g_h + (size_t)node * HD + head * OUT_DIM;
    const float* asrc = a + head * (2 * OUT_DIM);
    const float* adst = asrc + OUT_DIM;
    float ss = 0.f, sd = 0.f;
#pragma unroll 8
    for (int d = 0; d < OUT_DIM; d++) {
        float hv = hp[d];
        ss += hv * asrc[d];
        sd += hv * adst[d];
    }
    g_ssrc[i] = ss;
    g_sdst[i] = sd;
}

// ---------------- init max/-inf, sum/0 ----------------
__global__ void gat_init_kernel() {
    int i = blockIdx.x * blockDim.x + threadIdx.x;
    if (i >= N_NODES * HEADS) return;
    g_max[i] = -__int_as_float(0x7f800000);
    g_sum[i] = 0.f;
}

// ---------------- out = bias ----------------
__global__ void gat_outinit_kernel(float* __restrict__ out,
                                   const float* __restrict__ bias) {
    for (int i = blockIdx.x * blockDim.x + threadIdx.x; i < N_NODES * HD;
         i += gridDim.x * blockDim.x) {
        out[i] = bias[i & (HD - 1)];
    }
}

__device__ __forceinline__ void atomicMaxF(float* addr, float v) {
    if (v >= 0.f)
        atomicMax((int*)addr, __float_as_int(v));
    else
        atomicMin((unsigned int*)addr, __float_as_uint(v));
}

// ---------------- edge pass 1: leaky_relu + segment max (float4) ----------
__global__ void gat_edgemax_kernel(const int* __restrict__ edges) {
    int e = blockIdx.x * blockDim.x + threadIdx.x;
    if (e >= N_EDGES) return;
    int2 ed = ((const int2*)edges)[e];
    float4 ss = *(const float4*)&g_ssrc[ed.x * HEADS];
    float4 sd = *(const float4*)&g_sdst[ed.y * HEADS];
    float4 v;
    v.x = ss.x + sd.x; v.x = (v.x > 0.f) ? v.x : 0.2f * v.x;
    v.y = ss.y + sd.y; v.y = (v.y > 0.f) ? v.y : 0.2f * v.y;
    v.z = ss.z + sd.z; v.z = (v.z > 0.f) ? v.z : 0.2f * v.z;
    v.w = ss.w + sd.w; v.w = (v.w > 0.f) ? v.w : 0.2f * v.w;
    *(float4*)&g_e[e * HEADS] = v;
    float* mp = &g_max[ed.x * HEADS];
    atomicMaxF(mp + 0, v.x);
    atomicMaxF(mp + 1, v.y);
    atomicMaxF(mp + 2, v.z);
    atomicMaxF(mp + 3, v.w);
}

// ---------------- edge pass 2: exp & segment sum (float4) ----------------
__global__ void gat_edgeexp_kernel(const int* __restrict__ edges) {
    int e = blockIdx.x * blockDim.x + threadIdx.x;
    if (e >= N_EDGES) return;
    int src = edges[2 * e];
    float4 v = *(const float4*)&g_e[e * HEADS];
    float4 m = *(const float4*)&g_max[src * HEADS];
    v.x = __expf(v.x - m.x);
    v.y = __expf(v.y - m.y);
    v.z = __expf(v.z - m.z);
    v.w = __expf(v.w - m.w);
    *(float4*)&g_e[e * HEADS] = v;
    float* sp = &g_sum[src * HEADS];
    atomicAdd(sp + 0, v.x);
    atomicAdd(sp + 1, v.y);
    atomicAdd(sp + 2, v.z);
    atomicAdd(sp + 3, v.w);
}

// ---------------- reciprocal of denominators ----------------
__global__ void gat_rsum_kernel() {
    int i = blockIdx.x * blockDim.x + threadIdx.x;
    if (i >= N_NODES * HEADS) return;
    g_sum[i] = __frcp_rn(g_sum[i] + 1e-10f);
}

// ---------------- edge pass 3: scatter (warp/edge, vector red) ----------
__device__ __forceinline__ void redAdd4(float* p, float a, float b, float c,
                                        float d) {
    asm volatile("red.global.add.v4.f32 [%0], {%1, %2, %3, %4};" ::
                     "l"(p), "f"(a), "f"(b), "f"(c), "f"(d)
                 : "memory");
}

__global__ void gat_scatter_kernel(const int* __restrict__ edges,
                                   float* __restrict__ out) {
    int gt = blockIdx.x * blockDim.x + threadIdx.x;
    int e = gt >> 5;
    if (e >= N_EDGES) return;
    int lane = gt & 31;

    int2 ed = ((const int2*)edges)[e];
    int head = lane >> 3;
    float alpha = g_e[e * HEADS + head] * g_sum[ed.x * HEADS + head];

    const float* hp = g_h + (size_t)ed.x * HD + lane * 8;
    float* op = out + (size_t)ed.y * HD + lane * 8;

    float4 v0 = *(const float4*)(hp);
    float4 v1 = *(const float4*)(hp + 4);
    redAdd4(op, alpha * v0.x, alpha * v0.y, alpha * v0.z, alpha * v0.w);
    redAdd4(op + 4, alpha * v1.x, alpha * v1.y, alpha * v1.z, alpha * v1.w);
}

// ---------------- launch ----------------
extern "C" void kernel_launch(void* const* d_in, const int* in_sizes, int n_in,
                              void* d_out, int out_size) {
    const float* x     = (const float*)d_in[0];
    const int*   edges = (const int*)d_in[1];
    const float* W     = (const float*)d_in[2];
    const float* a     = (const float*)d_in[3];
    const float* bias  = (const float*)d_in[4];
    float* out = (float*)d_out;

    dim3 gemm_grid((N_NODES + GBM - 1) / GBM, HD / GBN);
    gat_gemm_tf32_kernel<<<gemm_grid, 256>>>(x, W);

    int nh = N_NODES * HEADS;
    gat_score_kernel<<<(nh + 255) / 256, 256>>>(a);
    gat_init_kernel<<<(nh + 255) / 256, 256>>>();
    gat_outinit_kernel<<<4096, 256>>>(out, bias);

    gat_edgemax_kernel<<<(N_EDGES + 255) / 256, 256>>>(edges);
    gat_edgeexp_kernel<<<(N_EDGES + 255) / 256, 256>>>(edges);
    gat_rsum_kernel<<<(nh + 255) / 256, 256>>>();

    gat_scatter_kernel<<<(N_EDGES * 32 + 255) / 256, 256>>>(edges, out);
}

// round 4
// speedup vs baseline: 3.9338x; 1.4046x over previous
#include <cuda_runtime.h>
#include <cuda_bf16.h>
#include <cstdint>

#define N_NODES 50000
#define N_EDGES 800000
#define IN_DIM 512
#define HEADS 4
#define OUT_DIM 64
#define HD 256  // HEADS*OUT_DIM

// ---------------- scratch (device globals; no runtime alloc) ----------------
__device__ float g_h[N_NODES * HD];          // 51.2 MB projected features
__device__ float g_ssrc[N_NODES * HEADS];
__device__ float g_sdst[N_NODES * HEADS];
__device__ float g_e[N_EDGES * HEADS];       // exp values -> alpha
__device__ float g_sum[N_NODES * HEADS];     // sum -> reciprocal
__device__ int   g_cnt[N_NODES];             // degree counts / fill cursors
__device__ int   g_offs[N_NODES + 1];        // CSR offsets (by dst)
__device__ int   g_part[256];                // scan partials
__device__ int2  g_csr[N_EDGES];             // (src, edge_id) grouped by dst

// ================= TF32 MMA GEMM: h = x @ W  (50000x512 @ 512x256) =========
#define GBM 128
#define GBN 64
#define GBK 32

__device__ __forceinline__ uint32_t f32_to_tf32(float f) {
    uint32_t r;
    asm("cvt.rna.tf32.f32 %0, %1;" : "=r"(r) : "f"(f));
    return r;
}

__global__ __launch_bounds__(256) void gat_gemm_tf32_kernel(
    const float* __restrict__ X, const float* __restrict__ W) {
    __shared__ uint32_t As[GBM][GBK + 4];   // [m][k]
    __shared__ uint32_t Bs[GBK][GBN + 4];   // [k][n]

    const int tid = threadIdx.x;
    const int lane = tid & 31;
    const int warp = tid >> 5;
    const int warp_m = warp >> 1;
    const int warp_n = warp & 1;

    const int bm = blockIdx.x * GBM;
    const int bn = blockIdx.y * GBN;

    float acc[2][4][4];
#pragma unroll
    for (int i = 0; i < 2; i++)
#pragma unroll
        for (int j = 0; j < 4; j++)
#pragma unroll
            for (int r = 0; r < 4; r++) acc[i][j][r] = 0.f;

    const int a_row_in = tid >> 3;
    const int a_k4 = (tid & 7) * 4;
    const int b_k_in = tid >> 4;
    const int b_n4 = (tid & 15) * 4;

    const int lg = lane >> 2;
    const int lt = lane & 3;

    for (int kt = 0; kt < IN_DIM; kt += GBK) {
#pragma unroll
        for (int i = 0; i < 4; i++) {
            int row = a_row_in + i * 32;
            int gm = bm + row;
            float4 v = make_float4(0.f, 0.f, 0.f, 0.f);
            if (gm < N_NODES)
                v = *(const float4*)(X + (size_t)gm * IN_DIM + kt + a_k4);
            As[row][a_k4 + 0] = f32_to_tf32(v.x);
            As[row][a_k4 + 1] = f32_to_tf32(v.y);
            As[row][a_k4 + 2] = f32_to_tf32(v.z);
            As[row][a_k4 + 3] = f32_to_tf32(v.w);
        }
#pragma unroll
        for (int i = 0; i < 2; i++) {
            int k = b_k_in + i * 16;
            float4 v = *(const float4*)(W + (size_t)(kt + k) * HD + bn + b_n4);
            Bs[k][b_n4 + 0] = f32_to_tf32(v.x);
            Bs[k][b_n4 + 1] = f32_to_tf32(v.y);
            Bs[k][b_n4 + 2] = f32_to_tf32(v.z);
            Bs[k][b_n4 + 3] = f32_to_tf32(v.w);
        }
        __syncthreads();

#pragma unroll
        for (int kk = 0; kk < GBK; kk += 8) {
            uint32_t af[2][4];
#pragma unroll
            for (int mt = 0; mt < 2; mt++) {
                int rb = warp_m * 32 + mt * 16;
                af[mt][0] = As[rb + lg][kk + lt];
                af[mt][1] = As[rb + lg + 8][kk + lt];
                af[mt][2] = As[rb + lg][kk + lt + 4];
                af[mt][3] = As[rb + lg + 8][kk + lt + 4];
            }
            uint32_t bf[4][2];
#pragma unroll
            for (int nt = 0; nt < 4; nt++) {
                int cb = warp_n * 32 + nt * 8;
                bf[nt][0] = Bs[kk + lt][cb + lg];
                bf[nt][1] = Bs[kk + lt + 4][cb + lg];
            }
#pragma unroll
            for (int mt = 0; mt < 2; mt++)
#pragma unroll
                for (int nt = 0; nt < 4; nt++) {
                    asm volatile(
                        "mma.sync.aligned.m16n8k8.row.col.f32.tf32.tf32.f32 "
                        "{%0,%1,%2,%3}, {%4,%5,%6,%7}, {%8,%9}, {%0,%1,%2,%3};"
                        : "+f"(acc[mt][nt][0]), "+f"(acc[mt][nt][1]),
                          "+f"(acc[mt][nt][2]), "+f"(acc[mt][nt][3])
                        : "r"(af[mt][0]), "r"(af[mt][1]), "r"(af[mt][2]),
                          "r"(af[mt][3]), "r"(bf[nt][0]), "r"(bf[nt][1]));
                }
        }
        __syncthreads();
    }

#pragma unroll
    for (int mt = 0; mt < 2; mt++) {
#pragma unroll
        for (int nt = 0; nt < 4; nt++) {
            int row0 = bm + warp_m * 32 + mt * 16 + lg;
            int col = bn + warp_n * 32 + nt * 8 + 2 * lt;
            if (row0 < N_NODES) {
                float2 v = make_float2(acc[mt][nt][0], acc[mt][nt][1]);
                *(float2*)&g_h[(size_t)row0 * HD + col] = v;
            }
            int row1 = row0 + 8;
            if (row1 < N_NODES) {
                float2 v = make_float2(acc[mt][nt][2], acc[mt][nt][3]);
                *(float2*)&g_h[(size_t)row1 * HD + col] = v;
            }
        }
    }
}

// ---------------- per-(node,head) attention scores ----------------
__global__ void gat_score_kernel(const float* __restrict__ a) {
    int i = blockIdx.x * blockDim.x + threadIdx.x;
    if (i >= N_NODES * HEADS) return;
    int node = i >> 2;
    int head = i & 3;
    const float* hp = g_h + (size_t)node * HD + head * OUT_DIM;
    const float* asrc = a + head * (2 * OUT_DIM);
    const float* adst = asrc + OUT_DIM;
    float ss = 0.f, sd = 0.f;
#pragma unroll 8
    for (int d = 0; d < OUT_DIM; d++) {
        float hv = hp[d];
        ss += hv * asrc[d];
        sd += hv * adst[d];
    }
    g_ssrc[i] = ss;
    g_sdst[i] = sd;
}

// ---------------- zero counters + sums ----------------
__global__ void gat_zero_kernel() {
    int i = blockIdx.x * blockDim.x + threadIdx.x;
    if (i < N_NODES) g_cnt[i] = 0;
    if (i < N_NODES * HEADS) g_sum[i] = 0.f;
}

// ---------------- degree histogram by dst ----------------
__global__ void gat_hist_kernel(const int* __restrict__ edges) {
    int e = blockIdx.x * blockDim.x + threadIdx.x;
    if (e >= N_EDGES) return;
    atomicAdd(&g_cnt[edges[2 * e + 1]], 1);
}

// ---------------- block scan phase 1 (256/block) ----------------
__global__ void gat_scan1_kernel() {
    __shared__ int s[256];
    int t = threadIdx.x;
    int i = blockIdx.x * 256 + t;
    int v = (i < N_NODES) ? g_cnt[i] : 0;
    s[t] = v;
    __syncthreads();
#pragma unroll
    for (int off = 1; off < 256; off <<= 1) {
        int u = (t >= off) ? s[t - off] : 0;
        __syncthreads();
        s[t] += u;
        __syncthreads();
    }
    if (i < N_NODES) g_offs[i] = s[t] - v;  // exclusive (block-local)
    if (t == 255) g_part[blockIdx.x] = s[255];
}

// ---------------- scan phase 2: scan partials (1 block) ----------------
__global__ void gat_scan2_kernel(int nblk) {
    __shared__ int s[256];
    int t = threadIdx.x;
    int v = (t < nblk) ? g_part[t] : 0;
    s[t] = v;
    __syncthreads();
#pragma unroll
    for (int off = 1; off < 256; off <<= 1) {
        int u = (t >= off) ? s[t - off] : 0;
        __syncthreads();
        s[t] += u;
        __syncthreads();
    }
    g_part[t] = s[t] - v;  // exclusive
}

// ---------------- scan phase 3: add partials, reset cnt ----------------
__global__ void gat_scan3_kernel() {
    int i = blockIdx.x * blockDim.x + threadIdx.x;
    if (i < N_NODES) {
        g_offs[i] += g_part[i >> 8];
        g_cnt[i] = 0;
    }
    if (i == 0) g_offs[N_NODES] = N_EDGES;
}

// ---------------- CSR fill (grouped by dst) ----------------
__global__ void gat_fill_kernel(const int* __restrict__ edges) {
    int e = blockIdx.x * blockDim.x + threadIdx.x;
    if (e >= N_EDGES) return;
    int2 ed = ((const int2*)edges)[e];
    int pos = g_offs[ed.y] + atomicAdd(&g_cnt[ed.y], 1);
    g_csr[pos] = make_int2(ed.x, e);
}

// ------- fused edge pass: leaky_relu + exp + segment sum (no max) -------
__global__ void gat_edgeexp_kernel(const int* __restrict__ edges) {
    int e = blockIdx.x * blockDim.x + threadIdx.x;
    if (e >= N_EDGES) return;
    int2 ed = ((const int2*)edges)[e];
    float4 ss = *(const float4*)&g_ssrc[ed.x * HEADS];
    float4 sd = *(const float4*)&g_sdst[ed.y * HEADS];
    float4 v;
    v.x = ss.x + sd.x; v.x = (v.x > 0.f) ? v.x : 0.2f * v.x;
    v.y = ss.y + sd.y; v.y = (v.y > 0.f) ? v.y : 0.2f * v.y;
    v.z = ss.z + sd.z; v.z = (v.z > 0.f) ? v.z : 0.2f * v.z;
    v.w = ss.w + sd.w; v.w = (v.w > 0.f) ? v.w : 0.2f * v.w;
    v.x = __expf(v.x);
    v.y = __expf(v.y);
    v.z = __expf(v.z);
    v.w = __expf(v.w);
    *(float4*)&g_e[e * HEADS] = v;
    float* sp = &g_sum[ed.x * HEADS];
    atomicAdd(sp + 0, v.x);
    atomicAdd(sp + 1, v.y);
    atomicAdd(sp + 2, v.z);
    atomicAdd(sp + 3, v.w);
}

// ---------------- reciprocal of denominators ----------------
__global__ void gat_rsum_kernel() {
    int i = blockIdx.x * blockDim.x + threadIdx.x;
    if (i >= N_NODES * HEADS) return;
    g_sum[i] = __frcp_rn(g_sum[i] + 1e-10f);
}

// ---------------- alpha = exp * rsum[src]  (in place on g_e) ----------
__global__ void gat_alpha_kernel(const int* __restrict__ edges) {
    int e = blockIdx.x * blockDim.x + threadIdx.x;
    if (e >= N_EDGES) return;
    int src = edges[2 * e];
    float4 ex = *(const float4*)&g_e[e * HEADS];
    float4 r = *(const float4*)&g_sum[src * HEADS];
    ex.x *= r.x; ex.y *= r.y; ex.z *= r.z; ex.w *= r.w;
    *(float4*)&g_e[e * HEADS] = ex;
}

// ------- aggregation: 64 threads/node, plain stores, bias folded -------
__global__ __launch_bounds__(256) void gat_aggregate_kernel(
    float* __restrict__ out, const float* __restrict__ bias) {
    int node = blockIdx.x * 4 + (threadIdx.x >> 6);
    if (node >= N_NODES) return;
    int t = threadIdx.x & 63;     // owns cols [4t, 4t+4)
    int head = t >> 4;

    int beg = g_offs[node];
    int end = g_offs[node + 1];

    float4 acc = make_float4(0.f, 0.f, 0.f, 0.f);
    int i = beg;
    for (; i + 1 < end; i += 2) {
        int2 s0 = g_csr[i];
        int2 s1 = g_csr[i + 1];
        float a0 = g_e[s0.y * HEADS + head];
        float a1 = g_e[s1.y * HEADS + head];
        float4 h0 = *(const float4*)&g_h[(size_t)s0.x * HD + t * 4];
        float4 h1 = *(const float4*)&g_h[(size_t)s1.x * HD + t * 4];
        acc.x += a0 * h0.x + a1 * h1.x;
        acc.y += a0 * h0.y + a1 * h1.y;
        acc.z += a0 * h0.z + a1 * h1.z;
        acc.w += a0 * h0.w + a1 * h1.w;
    }
    if (i < end) {
        int2 s0 = g_csr[i];
        float a0 = g_e[s0.y * HEADS + head];
        float4 h0 = *(const float4*)&g_h[(size_t)s0.x * HD + t * 4];
        acc.x += a0 * h0.x;
        acc.y += a0 * h0.y;
        acc.z += a0 * h0.z;
        acc.w += a0 * h0.w;
    }

    float4 b = *(const float4*)&bias[t * 4];
    acc.x += b.x; acc.y += b.y; acc.z += b.z; acc.w += b.w;
    *(float4*)&out[(size_t)node * HD + t * 4] = acc;
}

// ---------------- launch ----------------
extern "C" void kernel_launch(void* const* d_in, const int* in_sizes, int n_in,
                              void* d_out, int out_size) {
    const float* x     = (const float*)d_in[0];
    const int*   edges = (const int*)d_in[1];
    const float* W     = (const float*)d_in[2];
    const float* a     = (const float*)d_in[3];
    const float* bias  = (const float*)d_in[4];
    float* out = (float*)d_out;

    const int nh = N_NODES * HEADS;
    const int nblk_scan = (N_NODES + 255) / 256;  // 196

    dim3 gemm_grid((N_NODES + GBM - 1) / GBM, HD / GBN);
    gat_gemm_tf32_kernel<<<gemm_grid, 256>>>(x, W);

    // CSR build (independent of GEMM results)
    gat_zero_kernel<<<(nh + 255) / 256, 256>>>();
    gat_hist_kernel<<<(N_EDGES + 255) / 256, 256>>>(edges);
    gat_scan1_kernel<<<nblk_scan, 256>>>();
    gat_scan2_kernel<<<1, 256>>>(nblk_scan);
    gat_scan3_kernel<<<nblk_scan, 256>>>();
    gat_fill_kernel<<<(N_EDGES + 255) / 256, 256>>>(edges);

    // attention
    gat_score_kernel<<<(nh + 255) / 256, 256>>>(a);
    gat_edgeexp_kernel<<<(N_EDGES + 255) / 256, 256>>>(edges);
    gat_rsum_kernel<<<(nh + 255) / 256, 256>>>();
    gat_alpha_kernel<<<(N_EDGES + 255) / 256, 256>>>(edges);

    // aggregation (atomic-free)
    gat_aggregate_kernel<<<(N_NODES + 3) / 4, 256>>>(out, bias);
}